// round 14
// baseline (speedup 1.0000x reference)
#include <cuda_runtime.h>

#define VOCAB   101
#define EMB     32
#define HID     32
#define T_STEPS 512
#define NWARP   8   // 8 warps/block: SMSP s gets warp s (4 rows) + warp s+4 (3 rows)
#define RPB     28  // rows per block = 4*(4+3)

// Precomputed per-token gate contributions: tbl[v][j] = (i, f, g, o)
// i, f, o entries are PRE-SCALED by 0.5 (sigmoid via 0.5*tanh(0.5x)+0.5).
__device__ float4 g_tbl[VOCAB * HID];
// Packed recurrence weights (f32x2 across k), gates i,f,o pre-scaled by 0.5:
// g_wpk[(gate*16 + k2)*32 + j] = scale * ( Wh[2*k2][g*32+j], Wh[2*k2+1][g*32+j] )
__device__ unsigned long long g_wpk[4 * 16 * 32];

__device__ __forceinline__ unsigned long long pack2(float lo, float hi) {
    unsigned long long r;
    asm("mov.b64 %0, {%1, %2};" : "=l"(r) : "f"(lo), "f"(hi));
    return r;
}
__device__ __forceinline__ float lo2(unsigned long long v) {
    return __uint_as_float((unsigned int)v);
}
__device__ __forceinline__ float hi2(unsigned long long v) {
    return __uint_as_float((unsigned int)(v >> 32));
}
// Packed double-rate fp32 FMA (Blackwell FFMA2)
__device__ __forceinline__ unsigned long long ffma2(unsigned long long a,
                                                    unsigned long long b,
                                                    unsigned long long c) {
    unsigned long long d;
    asm("fma.rn.f32x2 %0, %1, %2, %3;" : "=l"(d) : "l"(a), "l"(b), "l"(c));
    return d;
}
__device__ __forceinline__ float tanh_fast(float x) {
    float y;
    asm("tanh.approx.f32 %0, %1;" : "=f"(y) : "f"(x));
    return y;
}
// input already pre-scaled by 0.5 via weights/table
__device__ __forceinline__ float sigmoid_half(float xh) {
    return fmaf(0.5f, tanh_fast(xh), 0.5f);
}

// ---------------------------------------------------------------------------
// Prep: token->xgate table and packed Wh (i,f,o scaled by 0.5). Tiny.
// ---------------------------------------------------------------------------
__global__ void prep_kernel(const float* __restrict__ emb,
                            const float* __restrict__ Wx,
                            const float* __restrict__ b,
                            const float* __restrict__ Wh) {
    int tid = blockIdx.x * blockDim.x + threadIdx.x;
    if (tid < VOCAB * HID) {
        int v = tid / HID, j = tid % HID;
        float si = b[j], sf = b[HID + j], sg = b[2 * HID + j], so = b[3 * HID + j];
        #pragma unroll
        for (int e = 0; e < EMB; e++) {
            float xe = emb[v * EMB + e];
            si = fmaf(xe, Wx[e * 4 * HID + j], si);
            sf = fmaf(xe, Wx[e * 4 * HID + HID + j], sf);
            sg = fmaf(xe, Wx[e * 4 * HID + 2 * HID + j], sg);
            so = fmaf(xe, Wx[e * 4 * HID + 3 * HID + j], so);
        }
        g_tbl[tid] = make_float4(0.5f * si, 0.5f * sf, sg, 0.5f * so);
    }
    if (tid < 4 * 16 * 32) {
        int j  = tid & 31;
        int k2 = (tid >> 5) & 15;
        int g  = tid >> 9;
        float sc = (g == 2) ? 1.0f : 0.5f;     // i,f,o pre-scaled for sigmoid
        float w0 = sc * Wh[(2 * k2) * 4 * HID + g * HID + j];
        float w1 = sc * Wh[(2 * k2 + 1) * 4 * HID + g * HID + j];
        g_wpk[tid] = pack2(w0, w1);
    }
}

// ---------------------------------------------------------------------------
// Per-warp LSTM over RPW rows, ROW-PIPELINED: each row's FMA chain is
// immediately followed by its activation tail, so row r's MUFU tail overlaps
// row r+1's FFMA2 block (MUFU drains under the fma pipe instead of after it).
// Lane j owns hidden unit j. h ping-pong in smem (broadcast LDS.128), token
// table in smem, Wh columns in registers, matvec in packed FFMA2.
// ---------------------------------------------------------------------------
template <int RPW>
__device__ __forceinline__ void lstm_rows(
    const int* __restrict__ x,
    const float* __restrict__ Wfc,
    const float* __restrict__ bfc,
    float* __restrict__ out,
    int rs, int lane, int B,
    const float4* __restrict__ tbl_s,
    float (&hsm)[2][4][HID],
    const unsigned long long (&w)[64])
{
    const unsigned FULL = 0xffffffffu;

    #pragma unroll
    for (int r = 0; r < RPW; ++r) hsm[0][r][lane] = 0.f;
    __syncwarp();

    float c[RPW];
    #pragma unroll
    for (int r = 0; r < RPW; ++r) c[r] = 0.f;

    const int* xrow[RPW];
    #pragma unroll
    for (int r = 0; r < RPW; ++r) {
        int bb = rs + r; if (bb >= B) bb = B - 1;   // dummy slots clamp
        xrow[r] = x + (long long)bb * T_STEPS;
    }

    for (int tc = 0; tc < T_STEPS / 32; ++tc) {
        int tokr[RPW];
        #pragma unroll
        for (int r = 0; r < RPW; ++r) tokr[r] = xrow[r][tc * 32 + lane];

        #pragma unroll 2
        for (int s = 0; s < 32; ++s) {
            const int buf = s & 1;
            const ulonglong2* hb = (const ulonglong2*)hsm[buf];

            // hoist token shuffles + table loads to the step head: their
            // latency hides under row 0's h-LDS and the first FMA chains
            float4 tb[RPW];
            #pragma unroll
            for (int r = 0; r < RPW; ++r) {
                int tok = __shfl_sync(FULL, tokr[r], s);
                tb[r] = tbl_s[tok * HID + lane];
            }

            // row-pipelined: FMA chain for row r, then its tail, then row r+1
            #pragma unroll
            for (int r = 0; r < RPW; ++r) {
                unsigned long long a0 = pack2(tb[r].x, 0.f);
                unsigned long long a1 = pack2(tb[r].y, 0.f);
                unsigned long long a2 = pack2(tb[r].z, 0.f);
                unsigned long long a3 = pack2(tb[r].w, 0.f);
                #pragma unroll
                for (int k4 = 0; k4 < 8; ++k4) {
                    ulonglong2 hq = hb[r * 8 + k4];      // broadcast LDS.128
                    a0 = ffma2(hq.x, w[     2 * k4    ], a0);
                    a0 = ffma2(hq.y, w[     2 * k4 + 1], a0);
                    a1 = ffma2(hq.x, w[16 + 2 * k4    ], a1);
                    a1 = ffma2(hq.y, w[16 + 2 * k4 + 1], a1);
                    a2 = ffma2(hq.x, w[32 + 2 * k4    ], a2);
                    a2 = ffma2(hq.y, w[32 + 2 * k4 + 1], a2);
                    a3 = ffma2(hq.x, w[48 + 2 * k4    ], a3);
                    a3 = ffma2(hq.y, w[48 + 2 * k4 + 1], a3);
                }
                float gi = lo2(a0) + hi2(a0);   // pre-scaled by 0.5
                float gf = lo2(a1) + hi2(a1);   // pre-scaled by 0.5
                float gg = lo2(a2) + hi2(a2);
                float go = lo2(a3) + hi2(a3);   // pre-scaled by 0.5
                float is = sigmoid_half(gi);
                float fs = sigmoid_half(gf);
                float os = sigmoid_half(go);
                float gt = tanh_fast(gg);
                c[r] = fmaf(fs, c[r], is * gt);
                float h = os * tanh_fast(c[r]);
                hsm[buf ^ 1][r][lane] = h;      // publish next-step h
            }
            __syncwarp();
        }
    }

    // FC head: final h sits in buffer 0
    float wf0 = Wfc[lane * 2 + 0], wf1 = Wfc[lane * 2 + 1];
    #pragma unroll
    for (int r = 0; r < RPW; ++r) {
        float h = hsm[0][r][lane];
        float u0 = h * wf0;
        float u1 = h * wf1;
        #pragma unroll
        for (int o = 16; o; o >>= 1) {
            u0 += __shfl_xor_sync(FULL, u0, o);
            u1 += __shfl_xor_sync(FULL, u1, o);
        }
        if (lane == 0 && rs + r < B) {
            out[(rs + r) * 2 + 0] = u0 + bfc[0];
            out[(rs + r) * 2 + 1] = u1 + bfc[1];
        }
    }
}

// ---------------------------------------------------------------------------
// Main: asymmetric warp pairing — SMSP s hosts warp s (4 rows) and warp s+4
// (3 rows) -> exactly 7 rows per SMSP, 28 per SM, 147 blocks = single wave.
// ---------------------------------------------------------------------------
__global__ void __launch_bounds__(NWARP * 32, 1)
lstm_kernel(const int* __restrict__ x,
            const float* __restrict__ Wfc,
            const float* __restrict__ bfc,
            float* __restrict__ out, int B) {
    const int lane = threadIdx.x & 31;
    const int wid  = threadIdx.x >> 5;

    // token table in shared memory (101*32 float4 = 51.7 KB)
    __shared__ __align__(16) float4 tbl_s[VOCAB * HID];
    // ping-pong h buffers per warp
    __shared__ __align__(16) float hsm[NWARP][2][4][HID];

    for (int i = threadIdx.x; i < VOCAB * HID; i += NWARP * 32)
        tbl_s[i] = g_tbl[i];

    // 64 packed weight words (128 fp32), shared by all rows of this warp
    unsigned long long w[64];
    #pragma unroll
    for (int i = 0; i < 64; i++) w[i] = g_wpk[i * 32 + lane];

    __syncthreads();   // table ready

    const int base = blockIdx.x * RPB;
    if (wid < 4) {
        int rs = base + wid * 4;                 // 4-row warps
        lstm_rows<4>(x, Wfc, bfc, out, rs, lane, B, tbl_s, hsm[wid], w);
    } else {
        int rs = base + 16 + (wid - 4) * 3;      // 3-row warps
        lstm_rows<3>(x, Wfc, bfc, out, rs, lane, B, tbl_s, hsm[wid], w);
    }
}

// ---------------------------------------------------------------------------
// Harness entry
// Inputs: x[int32 B*T], emb[101*32], Wx[32*128], Wh[32*128], b[128],
//         W_fc[32*2], b_fc[2]. Output: float [B,2].
// ---------------------------------------------------------------------------
extern "C" void kernel_launch(void* const* d_in, const int* in_sizes, int n_in,
                              void* d_out, int out_size) {
    const int*   x   = (const int*)  d_in[0];
    const float* emb = (const float*)d_in[1];
    const float* Wx  = (const float*)d_in[2];
    const float* Wh  = (const float*)d_in[3];
    const float* b   = (const float*)d_in[4];
    const float* Wfc = (const float*)d_in[5];
    const float* bfc = (const float*)d_in[6];
    float* out = (float*)d_out;

    const int B = in_sizes[0] / T_STEPS;

    prep_kernel<<<(VOCAB * HID + 255) / 256, 256>>>(emb, Wx, b, Wh);

    const int nblocks = (B + RPB - 1) / RPB;   // 147 for B=4096 -> single wave
    lstm_kernel<<<nblocks, NWARP * 32>>>(x, Wfc, bfc, out, B);
}

// round 15
// speedup vs baseline: 1.1515x; 1.1515x over previous
#include <cuda_runtime.h>

#define VOCAB   101
#define EMB     32
#define HID     32
#define T_STEPS 512
#define NWARP   8   // 8 warps/block: SMSP s gets warp s (4 rows) + warp s+4 (3 rows)
#define RPB     28  // rows per block = 4*(4+3)

// Precomputed per-token gate contributions: tbl[v][j] = (i, f, g, o)
// i, f, o entries PRE-SCALED by 0.5 (sigmoid(x) = 0.5*tanh(0.5x)+0.5).
__device__ float4 g_tbl[VOCAB * HID];
// Packed recurrence weights (f32x2 across k), gates i,f,o pre-scaled by 0.5:
// g_wpk[(gate*16 + k2)*32 + j] = scale * ( Wh[2*k2][g*32+j], Wh[2*k2+1][g*32+j] )
__device__ unsigned long long g_wpk[4 * 16 * 32];

__device__ __forceinline__ unsigned long long pack2(float lo, float hi) {
    unsigned long long r;
    asm("mov.b64 %0, {%1, %2};" : "=l"(r) : "f"(lo), "f"(hi));
    return r;
}
__device__ __forceinline__ float lo2(unsigned long long v) {
    return __uint_as_float((unsigned int)v);
}
__device__ __forceinline__ float hi2(unsigned long long v) {
    return __uint_as_float((unsigned int)(v >> 32));
}
// Packed double-rate fp32 FMA (Blackwell FFMA2)
__device__ __forceinline__ unsigned long long ffma2(unsigned long long a,
                                                    unsigned long long b,
                                                    unsigned long long c) {
    unsigned long long d;
    asm("fma.rn.f32x2 %0, %1, %2, %3;" : "=l"(d) : "l"(a), "l"(b), "l"(c));
    return d;
}
__device__ __forceinline__ float tanh_fast(float x) {
    float y;
    asm("tanh.approx.f32 %0, %1;" : "=f"(y) : "f"(x));
    return y;
}
// input already pre-scaled by 0.5 via weights/table
__device__ __forceinline__ float sigmoid_half(float xh) {
    return fmaf(0.5f, tanh_fast(xh), 0.5f);
}

// ---------------------------------------------------------------------------
// Prep: token->xgate table and packed Wh (i,f,o scaled by 0.5). Tiny.
// ---------------------------------------------------------------------------
__global__ void prep_kernel(const float* __restrict__ emb,
                            const float* __restrict__ Wx,
                            const float* __restrict__ b,
                            const float* __restrict__ Wh) {
    int tid = blockIdx.x * blockDim.x + threadIdx.x;
    if (tid < VOCAB * HID) {
        int v = tid / HID, j = tid % HID;
        float si = b[j], sf = b[HID + j], sg = b[2 * HID + j], so = b[3 * HID + j];
        #pragma unroll
        for (int e = 0; e < EMB; e++) {
            float xe = emb[v * EMB + e];
            si = fmaf(xe, Wx[e * 4 * HID + j], si);
            sf = fmaf(xe, Wx[e * 4 * HID + HID + j], sf);
            sg = fmaf(xe, Wx[e * 4 * HID + 2 * HID + j], sg);
            so = fmaf(xe, Wx[e * 4 * HID + 3 * HID + j], so);
        }
        g_tbl[tid] = make_float4(0.5f * si, 0.5f * sf, sg, 0.5f * so);
    }
    if (tid < 4 * 16 * 32) {
        int j  = tid & 31;
        int k2 = (tid >> 5) & 15;
        int g  = tid >> 9;
        float sc = (g == 2) ? 1.0f : 0.5f;     // i,f,o pre-scaled for sigmoid
        float w0 = sc * Wh[(2 * k2) * 4 * HID + g * HID + j];
        float w1 = sc * Wh[(2 * k2 + 1) * 4 * HID + g * HID + j];
        g_wpk[tid] = pack2(w0, w1);
    }
}

// FMA accumulation for one row: 4 gate accumulators, 32 FFMA2, inputs from
// broadcast LDS.128 of the row's h vector.
__device__ __forceinline__ void row_fma(
    const ulonglong2* __restrict__ hb, int r, const float4& tb,
    const unsigned long long (&w)[64], unsigned long long (&a)[4])
{
    a[0] = pack2(tb.x, 0.f);
    a[1] = pack2(tb.y, 0.f);
    a[2] = pack2(tb.z, 0.f);
    a[3] = pack2(tb.w, 0.f);
    #pragma unroll
    for (int k4 = 0; k4 < 8; ++k4) {
        ulonglong2 hq = hb[r * 8 + k4];          // broadcast LDS.128
        a[0] = ffma2(hq.x, w[     2 * k4    ], a[0]);
        a[0] = ffma2(hq.y, w[     2 * k4 + 1], a[0]);
        a[1] = ffma2(hq.x, w[16 + 2 * k4    ], a[1]);
        a[1] = ffma2(hq.y, w[16 + 2 * k4 + 1], a[1]);
        a[2] = ffma2(hq.x, w[32 + 2 * k4    ], a[2]);
        a[2] = ffma2(hq.y, w[32 + 2 * k4 + 1], a[2]);
        a[3] = ffma2(hq.x, w[48 + 2 * k4    ], a[3]);
        a[3] = ffma2(hq.y, w[48 + 2 * k4 + 1], a[3]);
    }
}

// Activation tail for one row; returns new h, updates c.
__device__ __forceinline__ float row_tail(
    const unsigned long long (&a)[4], float& c)
{
    float gi = lo2(a[0]) + hi2(a[0]);   // pre-scaled by 0.5
    float gf = lo2(a[1]) + hi2(a[1]);   // pre-scaled by 0.5
    float gg = lo2(a[2]) + hi2(a[2]);
    float go = lo2(a[3]) + hi2(a[3]);   // pre-scaled by 0.5
    float is = sigmoid_half(gi);
    float fs = sigmoid_half(gf);
    float os = sigmoid_half(go);
    float gt = tanh_fast(gg);
    c = fmaf(fs, c, is * gt);
    return os * tanh_fast(c);
}

// ---------------------------------------------------------------------------
// Per-warp LSTM over RPW rows with TWO-GROUP pipelining inside each step:
//   tb(all) -> FMA(group A) -> [tail(A) || FMA(group B)] -> tail(B) -> sync
// Group A's MUFU tail drains under group B's FFMA2 block; each group keeps
// >=4 accumulator chains so the fma pipe stays at reciprocal throughput.
// GA = ceil(RPW/2).
// ---------------------------------------------------------------------------
template <int RPW>
__device__ __forceinline__ void lstm_rows(
    const int* __restrict__ x,
    const float* __restrict__ Wfc,
    const float* __restrict__ bfc,
    float* __restrict__ out,
    int rs, int lane, int B,
    const float4* __restrict__ tbl_s,
    float (&hsm)[2][4][HID],
    const unsigned long long (&w)[64])
{
    const unsigned FULL = 0xffffffffu;
    constexpr int GA = (RPW + 1) / 2;        // group A rows [0, GA)
    constexpr int GB = RPW - GA;             // group B rows [GA, RPW)

    #pragma unroll
    for (int r = 0; r < RPW; ++r) hsm[0][r][lane] = 0.f;
    __syncwarp();

    float c[RPW];
    #pragma unroll
    for (int r = 0; r < RPW; ++r) c[r] = 0.f;

    const int* xrow[RPW];
    #pragma unroll
    for (int r = 0; r < RPW; ++r) {
        int bb = rs + r; if (bb >= B) bb = B - 1;   // dummy slots clamp
        xrow[r] = x + (long long)bb * T_STEPS;
    }

    for (int tc = 0; tc < T_STEPS / 32; ++tc) {
        int tokr[RPW];
        #pragma unroll
        for (int r = 0; r < RPW; ++r) tokr[r] = xrow[r][tc * 32 + lane];

        #pragma unroll 2
        for (int s = 0; s < 32; ++s) {
            const int buf = s & 1;
            const ulonglong2* hb = (const ulonglong2*)hsm[buf];

            // step head: all token table loads (latency hidden by FMA(A))
            float4 tb[RPW];
            #pragma unroll
            for (int r = 0; r < RPW; ++r) {
                int tok = __shfl_sync(FULL, tokr[r], s);
                tb[r] = tbl_s[tok * HID + lane];
            }

            // FMA for group A
            unsigned long long aA[GA][4];
            #pragma unroll
            for (int r = 0; r < GA; ++r) row_fma(hb, r, tb[r], w, aA[r]);

            // FMA for group B (independent of tail(A) -> overlaps it)
            unsigned long long aB[GB > 0 ? GB : 1][4];
            #pragma unroll
            for (int r = 0; r < GB; ++r) row_fma(hb, GA + r, tb[GA + r], w, aB[r]);

            // tail(A): MUFUs drain under FMA(B) above (scheduler interleaves)
            #pragma unroll
            for (int r = 0; r < GA; ++r) {
                float h = row_tail(aA[r], c[r]);
                hsm[buf ^ 1][r][lane] = h;
            }

            // tail(B): the only exposed MUFU burst of the step
            #pragma unroll
            for (int r = 0; r < GB; ++r) {
                float h = row_tail(aB[r], c[GA + r]);
                hsm[buf ^ 1][GA + r][lane] = h;
            }
            __syncwarp();
        }
    }

    // FC head: final h sits in buffer 0
    float wf0 = Wfc[lane * 2 + 0], wf1 = Wfc[lane * 2 + 1];
    #pragma unroll
    for (int r = 0; r < RPW; ++r) {
        float h = hsm[0][r][lane];
        float u0 = h * wf0;
        float u1 = h * wf1;
        #pragma unroll
        for (int o = 16; o; o >>= 1) {
            u0 += __shfl_xor_sync(FULL, u0, o);
            u1 += __shfl_xor_sync(FULL, u1, o);
        }
        if (lane == 0 && rs + r < B) {
            out[(rs + r) * 2 + 0] = u0 + bfc[0];
            out[(rs + r) * 2 + 1] = u1 + bfc[1];
        }
    }
}

// ---------------------------------------------------------------------------
// Main: asymmetric warp pairing — SMSP s hosts warp s (4 rows) and warp s+4
// (3 rows) -> exactly 7 rows per SMSP, 28 per SM, 147 blocks = single wave.
// ---------------------------------------------------------------------------
__global__ void __launch_bounds__(NWARP * 32, 1)
lstm_kernel(const int* __restrict__ x,
            const float* __restrict__ Wfc,
            const float* __restrict__ bfc,
            float* __restrict__ out, int B) {
    const int lane = threadIdx.x & 31;
    const int wid  = threadIdx.x >> 5;

    // token table in shared memory (101*32 float4 = 51.7 KB)
    __shared__ __align__(16) float4 tbl_s[VOCAB * HID];
    // ping-pong h buffers per warp
    __shared__ __align__(16) float hsm[NWARP][2][4][HID];

    for (int i = threadIdx.x; i < VOCAB * HID; i += NWARP * 32)
        tbl_s[i] = g_tbl[i];

    // 64 packed weight words (128 fp32), shared by all rows of this warp
    unsigned long long w[64];
    #pragma unroll
    for (int i = 0; i < 64; i++) w[i] = g_wpk[i * 32 + lane];

    __syncthreads();   // table ready

    const int base = blockIdx.x * RPB;
    if (wid < 4) {
        int rs = base + wid * 4;                 // 4-row warps
        lstm_rows<4>(x, Wfc, bfc, out, rs, lane, B, tbl_s, hsm[wid], w);
    } else {
        int rs = base + 16 + (wid - 4) * 3;      // 3-row warps
        lstm_rows<3>(x, Wfc, bfc, out, rs, lane, B, tbl_s, hsm[wid], w);
    }
}

// ---------------------------------------------------------------------------
// Harness entry
// Inputs: x[int32 B*T], emb[101*32], Wx[32*128], Wh[32*128], b[128],
//         W_fc[32*2], b_fc[2]. Output: float [B,2].
// ---------------------------------------------------------------------------
extern "C" void kernel_launch(void* const* d_in, const int* in_sizes, int n_in,
                              void* d_out, int out_size) {
    const int*   x   = (const int*)  d_in[0];
    const float* emb = (const float*)d_in[1];
    const float* Wx  = (const float*)d_in[2];
    const float* Wh  = (const float*)d_in[3];
    const float* b   = (const float*)d_in[4];
    const float* Wfc = (const float*)d_in[5];
    const float* bfc = (const float*)d_in[6];
    float* out = (float*)d_out;

    const int B = in_sizes[0] / T_STEPS;

    prep_kernel<<<(VOCAB * HID + 255) / 256, 256>>>(emb, Wx, b, Wh);

    const int nblocks = (B + RPB - 1) / RPB;   // 147 for B=4096 -> single wave
    lstm_kernel<<<nblocks, NWARP * 32>>>(x, Wfc, bfc, out, B);
}